// round 9
// baseline (speedup 1.0000x reference)
#include <cuda_runtime.h>
#include <cstdint>

// FieldAwareFM: B=16384, F=10 fields, D=8.
// y[b] = b_lin + sum_f w[xoff[b,f]] + sum_{f<g} <emb[f, xoff[b,g]], emb[g, xoff[b,f]]>
//
// Main kernel = best measured structure (one warp/sample, 2048x256,
// __launch_bounds__(256,6), per-task sqrt pair decode, g-DESC pair order).
// Packing restricted to HOT fields only (5..9, 3610 columns, 1.15 MB):
// cold-field packing was measured to inflate DRAM line traffic (R7).
// Packed block: 9 rows (9*32B) + folded linear w, 320B stride.

#define BATCH      16384
#define NUM_FIELDS 10
#define FACTOR_DIM 8
#define INPUT_DIM  188610
#define NPAIRS     45
#define NPACKCOLS  3610        // fields 5..9: 2000+1000+500+100+10
#define BLK_F      80          // floats per packed block (9*8 + w + pad)
#define BLK_B      (BLK_F*4)   // 320 bytes
#define W_OFF_B    288         // byte offset of folded w inside a block

__constant__ int c_off[NUM_FIELDS] = {
    0, 100000, 150000, 170000, 180000, 185000, 187000, 188000, 188500, 188600
};
// pack base per field (fields 5..9; 0..4 unused dummies)
__constant__ int c_pb10[NUM_FIELDS] = {
    0, 0, 0, 0, 0, 0, 2000, 3000, 3500, 3600
};

__device__ __align__(128) float g_pack[NPACKCOLS * BLK_F];

// ---------------- pack kernel ----------------
__global__ __launch_bounds__(256) void pack_kernel(
    const float* __restrict__ w,
    const float* __restrict__ emb)
{
    int tid = blockIdx.x * blockDim.x + threadIdx.x;   // [0, 3610*20)
    if (tid >= NPACKCOLS * 20) return;
    int jp = tid / 20;
    int u  = tid % 20;
    int c5 = (jp >= 2000) + (jp >= 3000) + (jp >= 3500) + (jp >= 3600);
    int c  = 5 + c5;                        // owning field
    int col = c_off[c] + (jp - c_pb10[c]);  // global column index

    if (u < 18) {
        int s = u >> 1, part = u & 1;
        int f = s + (s >= c);               // slot s holds field f (skip c)
        const float4 v = *reinterpret_cast<const float4*>(
            emb + ((size_t)f * INPUT_DIM + (size_t)col) * FACTOR_DIM + part * 4);
        *reinterpret_cast<float4*>(g_pack + (size_t)jp * BLK_F + s * 8 + part * 4) = v;
    } else if (u == 18) {
        g_pack[(size_t)jp * BLK_F + (W_OFF_B / 4)] = w[col];
    }
}

// ---------------- main kernel ----------------
__global__ __launch_bounds__(256, 6) void ffm_kernel(
    const int*   __restrict__ x,       // (B, 10) int32
    const float* __restrict__ w,       // (INPUT_DIM,)
    const float* __restrict__ blin,    // scalar
    const float* __restrict__ emb,     // (10, INPUT_DIM, 8)
    float*       __restrict__ out)     // (B,)
{
    const unsigned FULL = 0xFFFFFFFFu;
    int b    = (blockIdx.x * blockDim.x + threadIdx.x) >> 5;  // sample id
    int lane = threadIdx.x & 31;
    if (b >= BATCH) return;

    const char* pk = (const char*)g_pack;
    const char* eb = (const char*)emb;

    // Lane f (<10) owns field f. V = byte key:
    //   packed (f>=5): V = ~blockByteBase (negative); raw: V = xoff*32.
    int   V   = 0;
    float acc = 0.0f;
    if (lane < NUM_FIELDS) {
        int  xr     = x[b * NUM_FIELDS + lane];
        bool packed = lane >= 5;
        int  pbb    = (c_pb10[lane] + xr) * BLK_B;
        int  rawoff = (xr + c_off[lane]) * 32;
        V = packed ? ~pbb : rawoff;
        const float* ap = packed
            ? (const float*)(pk + pbb + W_OFF_B)          // w folded into block
            : (const float*)((const char*)w + (rawoff >> 3));
        acc = *ap;
    }

    const int partB = (lane & 1) << 4;   // 16B half select (t&1 == lane&1)

    float4 va[3], vb[3];
    bool   valid[3];

    #pragma unroll
    for (int k = 0; k < 3; k++) {
        int  t   = lane + 32 * k;            // task id, 90 valid
        bool vld = t < 2 * NPAIRS;
        int  p   = vld ? (t >> 1) : 0;       // pair id (clamped: shfl convergence)

        // Pairs sorted by g DESC then f ASC; exact fp32 sqrt decode:
        // r = 45 - p; g = ceil((sqrt(8r+1)-1)/2); f = p - 45 + g(g+1)/2.
        int   r = NPAIRS - p;
        float s = sqrtf((float)(8 * r + 1));
        int   g = (int)ceilf((s - 1.0f) * 0.5f);
        int   f = p - NPAIRS + (g * (g + 1)) / 2;

        int vg = __shfl_sync(FULL, V, g);    // key of A row: emb[f, x_g]
        int vf = __shfl_sync(FULL, V, f);    // key of B row: emb[g, x_f]

        const char* pA = (vg < 0)
            ? (pk + (~vg) + f * 32)                               // slot f (f<g)
            : (eb + (unsigned)(f * (INPUT_DIM * 32)) + (unsigned)vg);
        const char* pB = (vf < 0)
            ? (pk + (~vf) + (g - 1) * 32)                         // slot g-1 (g>f)
            : (eb + (unsigned)(g * (INPUT_DIM * 32)) + (unsigned)vf);

        valid[k] = vld;
        if (vld) {
            va[k] = *(const float4*)(pA + partB);
            vb[k] = *(const float4*)(pB + partB);
        }
    }

    #pragma unroll
    for (int k = 0; k < 3; k++) {
        if (valid[k]) {
            acc += va[k].x * vb[k].x + va[k].y * vb[k].y
                 + va[k].z * vb[k].z + va[k].w * vb[k].w;
        }
    }

    #pragma unroll
    for (int o = 16; o > 0; o >>= 1)
        acc += __shfl_xor_sync(FULL, acc, o);

    if (lane == 0)
        out[b] = acc + blin[0];
}

extern "C" void kernel_launch(void* const* d_in, const int* in_sizes, int n_in,
                              void* d_out, int out_size) {
    const int*   x    = (const int*)  d_in[0];
    const float* w    = (const float*)d_in[1];
    const float* blin = (const float*)d_in[2];
    const float* emb  = (const float*)d_in[3];
    float* out = (float*)d_out;

    const int pack_threads = 256;
    const int pack_blocks  = (NPACKCOLS * 20 + pack_threads - 1) / pack_threads;
    pack_kernel<<<pack_blocks, pack_threads>>>(w, emb);

    const int threads = 256;                      // 8 warps = 8 samples / block
    const int blocks  = (BATCH * 32) / threads;   // 2048
    ffm_kernel<<<blocks, threads>>>(x, w, blin, emb, out);
}